// round 8
// baseline (speedup 1.0000x reference)
#include <cuda_runtime.h>

#define BB 8
#define NN 1024
#define HIDD 256
#define HEADS 8
#define DHH 32
#define EPER 16384
#define KKP 512

// ---- output layout (float32, concatenated flattened outputs) ----
#define OFF_ENC   0
#define OFF_SUBX  (BB*NN*HIDD)
#define OFF_EDGE  (OFF_SUBX + BB*KKP*HIDD)
#define OFF_PERM  (OFF_EDGE + BB*2*EPER)
#define OFF_VALID (OFF_PERM + BB*KKP)

// ---- device scratch ----
__device__ float g_Q[BB*NN*HIDD];
__device__ float g_K[BB*NN*HIDD];
__device__ float g_V[BB*NN*HIDD];
__device__ float g_AO[BB*NN*HIDD];
__device__ float g_ENC[BB*NN*HIDD];
__device__ float g_score[BB*NN];
__device__ int   g_perm[BB*KKP];
__device__ float g_vals[BB*KKP];
__device__ int   g_nodemap[BB*NN];
__device__ unsigned long long g_es[BB*EPER];

// ---- packed f32x2 helpers ----
__device__ __forceinline__ unsigned long long fma2(
    unsigned long long a, unsigned long long b, unsigned long long c) {
    unsigned long long d;
    asm("fma.rn.f32x2 %0, %1, %2, %3;" : "=l"(d) : "l"(a), "l"(b), "l"(c));
    return d;
}
__device__ __forceinline__ unsigned long long mul2(
    unsigned long long a, unsigned long long b) {
    unsigned long long d;
    asm("mul.rn.f32x2 %0, %1, %2;" : "=l"(d) : "l"(a), "l"(b));
    return d;
}
__device__ __forceinline__ unsigned long long pack2(float lo, float hi) {
    unsigned long long r;
    asm("mov.b64 %0, {%1, %2};" : "=l"(r) : "f"(lo), "f"(hi));
    return r;
}
__device__ __forceinline__ float2 unpack2(unsigned long long v) {
    float2 r;
    asm("mov.b64 {%0, %1}, %2;" : "=f"(r.x), "=f"(r.y) : "l"(v));
    return r;
}
__device__ __forceinline__ void cp16(unsigned smem, const void* g) {
    asm volatile("cp.async.cg.shared.global [%0], [%1], 16;" :: "r"(smem), "l"(g));
}
__device__ __forceinline__ void cp_commit() {
    asm volatile("cp.async.commit_group;");
}
__device__ __forceinline__ void cp_wait1() {
    asm volatile("cp.async.wait_group 1;");
}
__device__ __forceinline__ void cp_wait0() {
    asm volatile("cp.async.wait_group 0;");
}

// ============================================================
// GEMM: C[8192,256] = A[8192,256] @ W[256,256]
// 128x64 block tile, 256 threads, 8x4 microtile (f32x2), K-chunk 16.
// ============================================================
__global__ __launch_bounds__(256) void gemm_k(
    const float* __restrict__ Aparam, const float* __restrict__ W,
    int sel, float* __restrict__ out2)
{
    const float* A;
    float* C;
    if      (sel == 0) { A = Aparam; C = g_Q; }
    else if (sel == 1) { A = Aparam; C = g_K; }
    else if (sel == 2) { A = Aparam; C = g_V; }
    else               { A = g_AO;   C = g_ENC; }

    __shared__ float As[16][128];
    __shared__ float Ws[16][64];
    const int t  = threadIdx.x;
    const int tx = t & 15;
    const int ty = t >> 4;
    const int rowBase = blockIdx.y * 128;
    const int colBase = blockIdx.x * 64;

    unsigned long long acc2[8][2];
    #pragma unroll
    for (int i = 0; i < 8; i++) { acc2[i][0] = 0ull; acc2[i][1] = 0ull; }

    const int wr = t >> 4, wc = (t & 15) << 2;

    for (int k0 = 0; k0 < 256; k0 += 16) {
        #pragma unroll
        for (int li = 0; li < 2; li++) {
            int idx = t * 2 + li;
            int row = idx >> 2;
            int c4  = (idx & 3) << 2;
            float4 a4 = *(const float4*)(A + (rowBase + row) * 256 + k0 + c4);
            As[c4 + 0][row] = a4.x; As[c4 + 1][row] = a4.y;
            As[c4 + 2][row] = a4.z; As[c4 + 3][row] = a4.w;
        }
        *(float4*)(&Ws[wr][wc]) = *(const float4*)(W + (k0 + wr) * 256 + colBase + wc);
        __syncthreads();
        #pragma unroll
        for (int kk = 0; kk < 16; kk++) {
            float4 a0 = *(const float4*)(&As[kk][ty << 3]);
            float4 a1 = *(const float4*)(&As[kk][(ty << 3) + 4]);
            ulonglong2 w2 = *(const ulonglong2*)(&Ws[kk][tx << 2]);
            unsigned long long b0 = pack2(a0.x, a0.x), b1 = pack2(a0.y, a0.y);
            unsigned long long b2 = pack2(a0.z, a0.z), b3 = pack2(a0.w, a0.w);
            unsigned long long b4 = pack2(a1.x, a1.x), b5 = pack2(a1.y, a1.y);
            unsigned long long b6 = pack2(a1.z, a1.z), b7 = pack2(a1.w, a1.w);
            acc2[0][0] = fma2(b0, w2.x, acc2[0][0]); acc2[0][1] = fma2(b0, w2.y, acc2[0][1]);
            acc2[1][0] = fma2(b1, w2.x, acc2[1][0]); acc2[1][1] = fma2(b1, w2.y, acc2[1][1]);
            acc2[2][0] = fma2(b2, w2.x, acc2[2][0]); acc2[2][1] = fma2(b2, w2.y, acc2[2][1]);
            acc2[3][0] = fma2(b3, w2.x, acc2[3][0]); acc2[3][1] = fma2(b3, w2.y, acc2[3][1]);
            acc2[4][0] = fma2(b4, w2.x, acc2[4][0]); acc2[4][1] = fma2(b4, w2.y, acc2[4][1]);
            acc2[5][0] = fma2(b5, w2.x, acc2[5][0]); acc2[5][1] = fma2(b5, w2.y, acc2[5][1]);
            acc2[6][0] = fma2(b6, w2.x, acc2[6][0]); acc2[6][1] = fma2(b6, w2.y, acc2[6][1]);
            acc2[7][0] = fma2(b7, w2.x, acc2[7][0]); acc2[7][1] = fma2(b7, w2.y, acc2[7][1]);
        }
        __syncthreads();
    }
    #pragma unroll
    for (int i = 0; i < 8; i++) {
        int row = rowBase + (ty << 3) + i;
        float2 lo = unpack2(acc2[i][0]), hi = unpack2(acc2[i][1]);
        float4 v = make_float4(lo.x, lo.y, hi.x, hi.y);
        *(float4*)(C + row * 256 + colBase + (tx << 2)) = v;
        if (sel == 3) *(float4*)(out2 + row * 256 + colBase + (tx << 2)) = v;
    }
}

// ============================================================
// Attention: warp-autonomous. Each warp = one head, 64 q (2/lane).
// Per-warp private smem ring (2 x (1KB K + 1KB V slice)), own
// cp.async + wait_group; dist read from global, prefetched.
// NO __syncthreads in the mainloop.
// ============================================================
__global__ __launch_bounds__(256, 1) void attn_kernel(const float* __restrict__ dist)
{
    __shared__ float sKV[8 * 1024];   // [warp][buf][K|V][8key x 32dim]

    const int b = blockIdx.y;
    const int qbase = blockIdx.x * 64;
    const int t = threadIdx.x;
    const int h = t >> 5, q = t & 31;            // q0 = q, q1 = q + 32

    const float* Kg = g_K + (long)b * NN * HIDD;
    const float* Vg = g_V + (long)b * NN * HIDD;

    float* warpBuf = sKV + h * 1024;             // 4KB region (1024 floats)
    unsigned wb = (unsigned)__cvta_generic_to_shared(warpBuf);

    // per-lane cp.async source offsets (bytes) within a k-tile
    const int key0 = q >> 3, part = q & 7;       // chunk c = q   -> key0 (0..3)
    // chunk c = q+32 -> key0+4
    const long rowOff0 = (long)key0 * 1024 + h * 128 + part * 16;
    const long rowOff1 = rowOff0 + 4 * 1024;

    unsigned long long qa[16], qb[16];
    {
        const ulonglong2* qp0 = (const ulonglong2*)(g_Q + ((long)(b * NN + qbase + q)) * HIDD + (h << 5));
        const ulonglong2* qp1 = (const ulonglong2*)(g_Q + ((long)(b * NN + qbase + q + 32)) * HIDD + (h << 5));
        #pragma unroll
        for (int d4 = 0; d4 < 8; d4++) {
            ulonglong2 v0 = qp0[d4], v1 = qp1[d4];
            qa[2*d4] = v0.x; qa[2*d4+1] = v0.y;
            qb[2*d4] = v1.x; qb[2*d4+1] = v1.y;
        }
    }

    // dist row pointers (float4 granularity, 2 float4 per 8-key tile)
    const float4* dqa = (const float4*)(dist + ((long)(b * NN + qbase + q)) * NN);
    const float4* dqb = (const float4*)(dist + ((long)(b * NN + qbase + q + 32)) * NN);

    // prologue: tile 0 K/V via cp.async into buf 0; dist tile 0 into regs
    {
        const char* Kt = (const char*)Kg;
        const char* Vt = (const char*)Vg;
        cp16(wb + q * 16,              Kt + rowOff0);
        cp16(wb + (q + 32) * 16,       Kt + rowOff1);
        cp16(wb + 1024 + q * 16,       Vt + rowOff0);
        cp16(wb + 1024 + (q + 32) * 16, Vt + rowOff1);
        cp_commit();
    }
    float da[8], db[8];
    *(float4*)&da[0] = dqa[0]; *(float4*)&da[4] = dqa[1];
    *(float4*)&db[0] = dqb[0]; *(float4*)&db[4] = dqb[1];

    float ma = -1e30f, la = 0.f, mb = -1e30f, lb = 0.f;
    unsigned long long oa[16], ob[16];
    #pragma unroll
    for (int d = 0; d < 16; d++) { oa[d] = 0ull; ob[d] = 0ull; }
    const float scale = 0.1767766952966369f;  // 1/sqrt(32)

    for (int kt = 0; kt < 128; kt++) {
        const int cur = kt & 1;
        float dan[8], dbn[8];
        if (kt < 127) {
            // issue next tile's K/V cp.async into alternate buffer
            const int nxt = cur ^ 1;
            const char* Kt = (const char*)Kg + (long)(kt + 1) * 8192;
            const char* Vt = (const char*)Vg + (long)(kt + 1) * 8192;
            unsigned base = wb + nxt * 2048;
            cp16(base + q * 16,               Kt + rowOff0);
            cp16(base + (q + 32) * 16,        Kt + rowOff1);
            cp16(base + 1024 + q * 16,        Vt + rowOff0);
            cp16(base + 1024 + (q + 32) * 16, Vt + rowOff1);
            cp_commit();
            // prefetch next dist tile
            *(float4*)&dan[0] = dqa[(kt + 1) * 2];
            *(float4*)&dan[4] = dqa[(kt + 1) * 2 + 1];
            *(float4*)&dbn[0] = dqb[(kt + 1) * 2];
            *(float4*)&dbn[4] = dqb[(kt + 1) * 2 + 1];
            cp_wait1();          // current tile's group complete
        } else {
            cp_wait0();
        }
        __syncwarp();

        const float* Kw = warpBuf + cur * 512;        // 8key x 32dim
        const float* Vw = warpBuf + cur * 512 + 256;

        float sva[8], svb[8];
        float smaxa = -1e30f, smaxb = -1e30f;
        #pragma unroll
        for (int kk = 0; kk < 8; kk++) {
            const ulonglong2* kp = (const ulonglong2*)(Kw + kk * 32);
            unsigned long long accA = 0ull, accB = 0ull, accC = 0ull, accD = 0ull;
            #pragma unroll
            for (int d4 = 0; d4 < 8; d4++) {
                ulonglong2 k2 = kp[d4];
                accA = fma2(qa[2*d4],   k2.x, accA);
                accB = fma2(qa[2*d4+1], k2.y, accB);
                accC = fma2(qb[2*d4],   k2.x, accC);
                accD = fma2(qb[2*d4+1], k2.y, accD);
            }
            float2 fa = unpack2(accA), fb = unpack2(accB);
            float2 fc = unpack2(accC), fd = unpack2(accD);
            float sA = ((fa.x + fa.y) + (fb.x + fb.y)) * scale + da[kk];
            float sB = ((fc.x + fc.y) + (fd.x + fd.y)) * scale + db[kk];
            sva[kk] = sA; svb[kk] = sB;
            smaxa = fmaxf(smaxa, sA);
            smaxb = fmaxf(smaxb, sB);
        }
        float mna = fmaxf(ma, smaxa);
        if (__any_sync(0xFFFFFFFFu, mna > ma)) {
            float corr = __expf(ma - mna);
            la *= corr;
            unsigned long long cc = pack2(corr, corr);
            #pragma unroll
            for (int d = 0; d < 16; d++) oa[d] = mul2(oa[d], cc);
            ma = mna;
        }
        float mnb = fmaxf(mb, smaxb);
        if (__any_sync(0xFFFFFFFFu, mnb > mb)) {
            float corr = __expf(mb - mnb);
            lb *= corr;
            unsigned long long cc = pack2(corr, corr);
            #pragma unroll
            for (int d = 0; d < 16; d++) ob[d] = mul2(ob[d], cc);
            mb = mnb;
        }
        #pragma unroll
        for (int kk = 0; kk < 8; kk++) {
            float pA = __expf(sva[kk] - ma);
            float pB = __expf(svb[kk] - mb);
            la += pA; lb += pB;
            unsigned long long p2a = pack2(pA, pA);
            unsigned long long p2b = pack2(pB, pB);
            const ulonglong2* vp = (const ulonglong2*)(Vw + kk * 32);
            #pragma unroll
            for (int d4 = 0; d4 < 8; d4++) {
                ulonglong2 v2 = vp[d4];
                oa[2*d4]   = fma2(v2.x, p2a, oa[2*d4]);
                oa[2*d4+1] = fma2(v2.y, p2a, oa[2*d4+1]);
                ob[2*d4]   = fma2(v2.x, p2b, ob[2*d4]);
                ob[2*d4+1] = fma2(v2.y, p2b, ob[2*d4+1]);
            }
        }

        if (kt < 127) {
            #pragma unroll
            for (int i = 0; i < 8; i++) { da[i] = dan[i]; db[i] = dbn[i]; }
        }
    }

    float inva = 1.f / la, invb = 1.f / lb;
    float* op0 = g_AO + ((long)(b * NN + qbase + q)) * HIDD + (h << 5);
    float* op1 = g_AO + ((long)(b * NN + qbase + q + 32)) * HIDD + (h << 5);
    #pragma unroll
    for (int d4 = 0; d4 < 8; d4++) {
        float2 a0 = unpack2(oa[2*d4]), a1 = unpack2(oa[2*d4+1]);
        float2 b0 = unpack2(ob[2*d4]), b1 = unpack2(ob[2*d4+1]);
        ((float4*)op0)[d4] = make_float4(a0.x * inva, a0.y * inva, a1.x * inva, a1.y * inva);
        ((float4*)op1)[d4] = make_float4(b0.x * invb, b0.y * invb, b1.x * invb, b1.y * invb);
    }
}

// ============================================================
// Node scores: s = tanh((x . w) / ||w||). One warp per node.
// ============================================================
__global__ __launch_bounds__(256) void score_kernel(const float* __restrict__ w)
{
    int warp = (blockIdx.x * blockDim.x + threadIdx.x) >> 5;
    int lane = threadIdx.x & 31;
    if (warp >= BB * NN) return;
    const float* x = g_ENC + (long)warp * HIDD;
    float sx = 0.f, sw = 0.f;
    #pragma unroll
    for (int i = lane; i < HIDD; i += 32) {
        float wv = w[i];
        sx += x[i] * wv;
        sw += wv * wv;
    }
    #pragma unroll
    for (int off = 16; off; off >>= 1) {
        sx += __shfl_xor_sync(0xFFFFFFFFu, sx, off);
        sw += __shfl_xor_sync(0xFFFFFFFFu, sw, off);
    }
    if (lane == 0) g_score[warp] = tanhf(sx / sqrtf(sw));
}

// ============================================================
// Top-K per graph: bitonic sort of 1024 (desc score, asc index).
// ============================================================
__global__ __launch_bounds__(1024) void topk_kernel(float* __restrict__ out_perm)
{
    __shared__ unsigned long long s[NN];
    const int b = blockIdx.x, t = threadIdx.x;
    float sc = g_score[b * NN + t];
    unsigned u = __float_as_uint(sc);
    u = (u & 0x80000000u) ? ~u : (u | 0x80000000u);
    u = ~u;                                            // descending
    s[t] = (((unsigned long long)u) << 32) | (unsigned)t;
    g_nodemap[b * NN + t] = -1;
    __syncthreads();
    for (unsigned k = 2; k <= NN; k <<= 1)
        for (unsigned j = k >> 1; j; j >>= 1) {
            unsigned i = t, ixj = i ^ j;
            if (ixj > i) {
                bool up = ((i & k) == 0);
                unsigned long long a = s[i], c = s[ixj];
                if ((a > c) == up) { s[i] = c; s[ixj] = a; }
            }
            __syncthreads();
        }
    if (t < KKP) {
        int node = (int)(s[t] & 0xFFFFFFFFu);
        g_perm[b * KKP + t] = node;
        g_vals[b * KKP + t] = g_score[b * NN + node];
        out_perm[b * KKP + t] = (float)node;
        g_nodemap[b * NN + node] = t;
    }
}

// ============================================================
// sub_x gather
// ============================================================
__global__ __launch_bounds__(256) void subx_kernel(float* __restrict__ out)
{
    const int row = blockIdx.x;
    const int b = row / KKP;
    const int node = g_perm[row];
    const float val = g_vals[row];
    const float* src = g_ENC + ((long)b * NN + node) * HIDD;
    out[(long)row * HIDD + threadIdx.x] = src[threadIdx.x] * val;
}

// ============================================================
// Edge pipeline (multi-kernel bitonic).
// ============================================================
__global__ __launch_bounds__(256) void edge_build(const void* __restrict__ eiraw)
{
    __shared__ int s_is64;
    if (threadIdx.x == 0) {
        const unsigned* w32 = (const unsigned*)eiraw;
        int all0 = 1;
        for (int i = 0; i < 64; i++)
            if (w32[2 * i + 1] != 0u) { all0 = 0; break; }
        s_is64 = all0;
    }
    __syncthreads();
    const int is64 = s_is64;
    const int total = BB * EPER;
    for (int idx = blockIdx.x * blockDim.x + threadIdx.x; idx < total;
         idx += gridDim.x * blockDim.x) {
        int b = idx >> 14;
        long long vs, vd;
        if (is64) {
            const long long* ei = (const long long*)eiraw;
            vs = ei[idx];
            vd = ei[total + idx];
        } else {
            const int* ei = (const int*)eiraw;
            vs = ei[idx];
            vd = ei[total + idx];
        }
        int src = (int)(vs - (long long)b * NN);
        int dst = (int)(vd - (long long)b * NN);
        src = min(max(src, 0), NN - 1);
        dst = min(max(dst, 0), NN - 1);
        int nu = g_nodemap[b * NN + src];
        int nv = g_nodemap[b * NN + dst];
        bool valid = (nu >= 0) && (nv >= 0);
        unsigned key = valid ? (unsigned)(nu * KKP + nv) : (unsigned)(KKP * KKP);
        int ou = valid ? nu : -1, ov = valid ? nv : -1;
        g_es[idx] = (((unsigned long long)key) << 21)
                  | (((unsigned long long)(ou + 1)) << 11)
                  | (((unsigned long long)(ov + 1)) << 1)
                  | (valid ? 1ull : 0ull);
    }
}

__global__ __launch_bounds__(1024) void edge_sort_seg()
{
    __shared__ unsigned long long sh[4096];
    const int b = blockIdx.x >> 2, seg = blockIdx.x & 3;
    const int t = threadIdx.x;
    unsigned long long* es = g_es + (long)b * EPER + seg * 4096;
    for (int i = t; i < 4096; i += 1024) sh[i] = es[i];
    __syncthreads();
    for (unsigned k = 2; k <= 4096; k <<= 1)
        for (unsigned j = k >> 1; j; j >>= 1) {
            for (int loc = t; loc < 4096; loc += 1024) {
                unsigned i2 = (unsigned)loc, ixj = i2 ^ j;
                if (ixj > i2) {
                    unsigned gi = seg * 4096 + i2;
                    bool up = ((gi & k) == 0);
                    unsigned long long a = sh[i2], c = sh[ixj];
                    if ((a > c) == up) { sh[i2] = c; sh[ixj] = a; }
                }
            }
            __syncthreads();
        }
    for (int i = t; i < 4096; i += 1024) es[i] = sh[i];
}

__global__ __launch_bounds__(1024) void edge_gmerge(unsigned k, unsigned j)
{
    int loc = blockIdx.x * blockDim.x + threadIdx.x;
    unsigned i = (unsigned)(loc & (EPER - 1));
    int b = loc >> 14;
    unsigned ixj = i ^ j;
    if (ixj > i) {
        unsigned long long* es = g_es + (long)b * EPER;
        bool up = ((i & k) == 0);
        unsigned long long a = es[i], c = es[ixj];
        if ((a > c) == up) { es[i] = c; es[ixj] = a; }
    }
}

__global__ __launch_bounds__(1024) void edge_smerge(unsigned k)
{
    __shared__ unsigned long long sh[4096];
    const int b = blockIdx.x >> 2, seg = blockIdx.x & 3;
    const int t = threadIdx.x;
    unsigned long long* es = g_es + (long)b * EPER + seg * 4096;
    for (int i = t; i < 4096; i += 1024) sh[i] = es[i];
    __syncthreads();
    for (unsigned j = 2048; j; j >>= 1) {
        for (int loc = t; loc < 4096; loc += 1024) {
            unsigned i2 = (unsigned)loc, ixj = i2 ^ j;
            if (ixj > i2) {
                unsigned gi = seg * 4096 + i2;
                bool up = ((gi & k) == 0);
                unsigned long long a = sh[i2], c = sh[ixj];
                if ((a > c) == up) { sh[i2] = c; sh[ixj] = a; }
            }
        }
        __syncthreads();
    }
    for (int i = t; i < 4096; i += 1024) es[i] = sh[i];
}

__global__ __launch_bounds__(256) void edge_emit(
    float* __restrict__ out_e, float* __restrict__ out_valid)
{
    const int total = BB * EPER;
    for (int idx = blockIdx.x * blockDim.x + threadIdx.x; idx < total;
         idx += gridDim.x * blockDim.x) {
        int b = idx >> 14, e = idx & (EPER - 1);
        unsigned long long p = g_es[idx];
        int ou = (int)((p >> 11) & 0x3FFu) - 1;
        int ov = (int)((p >> 1) & 0x3FFu) - 1;
        out_e[(long)b * 2 * EPER + e]        = (float)ou;
        out_e[(long)b * 2 * EPER + EPER + e] = (float)ov;
        out_valid[(long)b * EPER + e]        = (float)(p & 1ull);
    }
}

// ============================================================
extern "C" void kernel_launch(void* const* d_in, const int* in_sizes, int n_in,
                              void* d_out, int out_size)
{
    const float* X    = (const float*)d_in[0];
    const void*  EI   = d_in[1];
    const float* DIST = (const float*)d_in[3];
    const float* Wq   = (const float*)d_in[5];
    const float* Wk   = (const float*)d_in[6];
    const float* Wv   = (const float*)d_in[7];
    const float* Wo   = (const float*)d_in[8];
    const float* tw   = (const float*)d_in[9];
    float* out = (float*)d_out;

    gemm_k<<<dim3(4, 64), 256>>>(X, Wq, 0, out + OFF_ENC);
    gemm_k<<<dim3(4, 64), 256>>>(X, Wk, 1, out + OFF_ENC);
    gemm_k<<<dim3(4, 64), 256>>>(X, Wv, 2, out + OFF_ENC);

    attn_kernel<<<dim3(16, 8), 256>>>(DIST);

    gemm_k<<<dim3(4, 64), 256>>>(X, Wo, 3, out + OFF_ENC);

    score_kernel<<<(BB * NN * 32) / 256, 256>>>(tw);
    topk_kernel<<<BB, NN>>>(out + OFF_PERM);
    subx_kernel<<<BB * KKP, 256>>>(out + OFF_SUBX);

    edge_build<<<128, 256>>>(EI);
    edge_sort_seg<<<32, 1024>>>();
    edge_gmerge<<<128, 1024>>>(8192u, 4096u);
    edge_smerge<<<32, 1024>>>(8192u);
    edge_gmerge<<<128, 1024>>>(16384u, 8192u);
    edge_gmerge<<<128, 1024>>>(16384u, 4096u);
    edge_smerge<<<32, 1024>>>(16384u);
    edge_emit<<<128, 256>>>(out + OFF_EDGE, out + OFF_VALID);
}

// round 10
// speedup vs baseline: 1.0650x; 1.0650x over previous
#include <cuda_runtime.h>

#define BB 8
#define NN 1024
#define HIDD 256
#define HEADS 8
#define DHH 32
#define EPER 16384
#define KKP 512

// ---- output layout (float32, concatenated flattened outputs) ----
#define OFF_ENC   0
#define OFF_SUBX  (BB*NN*HIDD)
#define OFF_EDGE  (OFF_SUBX + BB*KKP*HIDD)
#define OFF_PERM  (OFF_EDGE + BB*2*EPER)
#define OFF_VALID (OFF_PERM + BB*KKP)

// ---- device scratch ----
__device__ float g_Q[BB*NN*HIDD];
__device__ float g_K[BB*NN*HIDD];
__device__ float g_V[BB*NN*HIDD];
__device__ float g_AO[BB*NN*HIDD];
__device__ float g_ENC[BB*NN*HIDD];
__device__ float g_score[BB*NN];
__device__ int   g_perm[BB*KKP];
__device__ float g_vals[BB*KKP];
__device__ int   g_nodemap[BB*NN];
__device__ unsigned long long g_es[BB*EPER];

// ---- packed f32x2 helpers ----
__device__ __forceinline__ unsigned long long fma2(
    unsigned long long a, unsigned long long b, unsigned long long c) {
    unsigned long long d;
    asm("fma.rn.f32x2 %0, %1, %2, %3;" : "=l"(d) : "l"(a), "l"(b), "l"(c));
    return d;
}
__device__ __forceinline__ unsigned long long mul2(
    unsigned long long a, unsigned long long b) {
    unsigned long long d;
    asm("mul.rn.f32x2 %0, %1, %2;" : "=l"(d) : "l"(a), "l"(b));
    return d;
}
__device__ __forceinline__ unsigned long long pack2(float lo, float hi) {
    unsigned long long r;
    asm("mov.b64 %0, {%1, %2};" : "=l"(r) : "f"(lo), "f"(hi));
    return r;
}
__device__ __forceinline__ float2 unpack2(unsigned long long v) {
    float2 r;
    asm("mov.b64 {%0, %1}, %2;" : "=f"(r.x), "=f"(r.y) : "l"(v));
    return r;
}
__device__ __forceinline__ void cp16(unsigned smem, const void* g) {
    asm volatile("cp.async.cg.shared.global [%0], [%1], 16;" :: "r"(smem), "l"(g));
}
__device__ __forceinline__ void cp_commit() {
    asm volatile("cp.async.commit_group;");
}
__device__ __forceinline__ void cp_wait0() {
    asm volatile("cp.async.wait_group 0;");
}

// ============================================================
// GEMM: C[8192,256] = A[8192,256] @ W[256,256]
// sel 0/1/2 (QKV, fused via gridDim.z): A=X, W=Wq/Wk/Wv, C=g_Q/K/V.
// sel 3: A=g_AO, W=W0 param slot, C=g_ENC + out2.
// Math identical to rounds 4-8 (frozen: feeds selection knife-edge).
// ============================================================
__global__ __launch_bounds__(256) void gemm_k(
    const float* __restrict__ Xp, const float* __restrict__ W0,
    const float* __restrict__ W1, const float* __restrict__ W2,
    int sel_base, float* __restrict__ out2)
{
    const int sel = sel_base + blockIdx.z;
    const float* A;
    const float* W;
    float* C;
    if      (sel == 0) { A = Xp;   W = W0; C = g_Q; }
    else if (sel == 1) { A = Xp;   W = W1; C = g_K; }
    else if (sel == 2) { A = Xp;   W = W2; C = g_V; }
    else               { A = g_AO; W = W0; C = g_ENC; }

    __shared__ float As[16][128];
    __shared__ float Ws[16][64];
    const int t  = threadIdx.x;
    const int tx = t & 15;
    const int ty = t >> 4;
    const int rowBase = blockIdx.y * 128;
    const int colBase = blockIdx.x * 64;

    unsigned long long acc2[8][2];
    #pragma unroll
    for (int i = 0; i < 8; i++) { acc2[i][0] = 0ull; acc2[i][1] = 0ull; }

    const int wr = t >> 4, wc = (t & 15) << 2;

    for (int k0 = 0; k0 < 256; k0 += 16) {
        #pragma unroll
        for (int li = 0; li < 2; li++) {
            int idx = t * 2 + li;
            int row = idx >> 2;
            int c4  = (idx & 3) << 2;
            float4 a4 = *(const float4*)(A + (rowBase + row) * 256 + k0 + c4);
            As[c4 + 0][row] = a4.x; As[c4 + 1][row] = a4.y;
            As[c4 + 2][row] = a4.z; As[c4 + 3][row] = a4.w;
        }
        *(float4*)(&Ws[wr][wc]) = *(const float4*)(W + (k0 + wr) * 256 + colBase + wc);
        __syncthreads();
        #pragma unroll
        for (int kk = 0; kk < 16; kk++) {
            float4 a0 = *(const float4*)(&As[kk][ty << 3]);
            float4 a1 = *(const float4*)(&As[kk][(ty << 3) + 4]);
            ulonglong2 w2 = *(const ulonglong2*)(&Ws[kk][tx << 2]);
            unsigned long long b0 = pack2(a0.x, a0.x), b1 = pack2(a0.y, a0.y);
            unsigned long long b2 = pack2(a0.z, a0.z), b3 = pack2(a0.w, a0.w);
            unsigned long long b4 = pack2(a1.x, a1.x), b5 = pack2(a1.y, a1.y);
            unsigned long long b6 = pack2(a1.z, a1.z), b7 = pack2(a1.w, a1.w);
            acc2[0][0] = fma2(b0, w2.x, acc2[0][0]); acc2[0][1] = fma2(b0, w2.y, acc2[0][1]);
            acc2[1][0] = fma2(b1, w2.x, acc2[1][0]); acc2[1][1] = fma2(b1, w2.y, acc2[1][1]);
            acc2[2][0] = fma2(b2, w2.x, acc2[2][0]); acc2[2][1] = fma2(b2, w2.y, acc2[2][1]);
            acc2[3][0] = fma2(b3, w2.x, acc2[3][0]); acc2[3][1] = fma2(b3, w2.y, acc2[3][1]);
            acc2[4][0] = fma2(b4, w2.x, acc2[4][0]); acc2[4][1] = fma2(b4, w2.y, acc2[4][1]);
            acc2[5][0] = fma2(b5, w2.x, acc2[5][0]); acc2[5][1] = fma2(b5, w2.y, acc2[5][1]);
            acc2[6][0] = fma2(b6, w2.x, acc2[6][0]); acc2[6][1] = fma2(b6, w2.y, acc2[6][1]);
            acc2[7][0] = fma2(b7, w2.x, acc2[7][0]); acc2[7][1] = fma2(b7, w2.y, acc2[7][1]);
        }
        __syncthreads();
    }
    #pragma unroll
    for (int i = 0; i < 8; i++) {
        int row = rowBase + (ty << 3) + i;
        float2 lo = unpack2(acc2[i][0]), hi = unpack2(acc2[i][1]);
        float4 v = make_float4(lo.x, lo.y, hi.x, hi.y);
        *(float4*)(C + row * 256 + colBase + (tx << 2)) = v;
        if (sel == 3) *(float4*)(out2 + row * 256 + colBase + (tx << 2)) = v;
    }
}

// ============================================================
// Attention: round-7 formulation VERBATIM (math frozen — feeds
// the top-k selection knife-edge). 2 q/thread, k-tile 8 double-
// buffered via cp.async, dist staged transposed, online softmax.
// ============================================================
__global__ __launch_bounds__(256, 1) void attn_kernel(const float* __restrict__ dist)
{
    __shared__ float Ks[2][8 * 256];
    __shared__ float Vs[2][8 * 256];
    __shared__ float ds[2][8 * 64];   // [k][q] transposed

    const int b = blockIdx.y;
    const int qbase = blockIdx.x * 64;
    const int t = threadIdx.x;
    const int h = t >> 5, q = t & 31;
    const int drow = t >> 2, dcol = (t & 3) << 1;

    const float* Kg = g_K + (long)b * NN * HIDD;
    const float* Vg = g_V + (long)b * NN * HIDD;
    const float* dg = dist + ((long)(b * NN + qbase + drow)) * NN + dcol;

    unsigned ks_base = (unsigned)__cvta_generic_to_shared(&Ks[0][0]);
    unsigned vs_base = (unsigned)__cvta_generic_to_shared(&Vs[0][0]);

    unsigned long long qa[16], qb[16];
    {
        const ulonglong2* qp0 = (const ulonglong2*)(g_Q + ((long)(b * NN + qbase + q)) * HIDD + (h << 5));
        const ulonglong2* qp1 = (const ulonglong2*)(g_Q + ((long)(b * NN + qbase + q + 32)) * HIDD + (h << 5));
        #pragma unroll
        for (int d4 = 0; d4 < 8; d4++) {
            ulonglong2 v0 = qp0[d4], v1 = qp1[d4];
            qa[2*d4] = v0.x; qa[2*d4+1] = v0.y;
            qb[2*d4] = v1.x; qb[2*d4+1] = v1.y;
        }
    }

    {
        cp16(ks_base + t * 16,             (const char*)Kg + t * 16);
        cp16(ks_base + (t + 256) * 16,     (const char*)Kg + (t + 256) * 16);
        cp16(vs_base + t * 16,             (const char*)Vg + t * 16);
        cp16(vs_base + (t + 256) * 16,     (const char*)Vg + (t + 256) * 16);
        cp_commit();
        float2 d0 = *(const float2*)dg;
        ds[0][dcol * 64 + drow]       = d0.x;
        ds[0][(dcol + 1) * 64 + drow] = d0.y;
        cp_wait0();
    }
    __syncthreads();

    float ma = -1e30f, la = 0.f, mb = -1e30f, lb = 0.f;
    unsigned long long oa[16], ob[16];
    #pragma unroll
    for (int d = 0; d < 16; d++) { oa[d] = 0ull; ob[d] = 0ull; }
    const float scale = 0.1767766952966369f;  // 1/sqrt(32)

    for (int kt = 0; kt < 128; kt++) {
        const int cur = kt & 1;
        float2 pd;
        if (kt < 127) {
            const int nxt = cur ^ 1;
            const char* Kn = (const char*)Kg + (kt + 1) * 8192;
            const char* Vn = (const char*)Vg + (kt + 1) * 8192;
            unsigned ksn = ks_base + nxt * 8192;
            unsigned vsn = vs_base + nxt * 8192;
            cp16(ksn + t * 16,         Kn + t * 16);
            cp16(ksn + (t + 256) * 16, Kn + (t + 256) * 16);
            cp16(vsn + t * 16,         Vn + t * 16);
            cp16(vsn + (t + 256) * 16, Vn + (t + 256) * 16);
            cp_commit();
            pd = *(const float2*)(dg + (kt + 1) * 8);
        }

        const float* Kc = Ks[cur];
        const float* Vc = Vs[cur];
        const float* dc = ds[cur];

        float sva[8], svb[8];
        float smaxa = -1e30f, smaxb = -1e30f;
        #pragma unroll
        for (int kk = 0; kk < 8; kk++) {
            const ulonglong2* kp = (const ulonglong2*)(Kc + kk * 256 + (h << 5));
            unsigned long long accA = 0ull, accB = 0ull, accC = 0ull, accD = 0ull;
            #pragma unroll
            for (int d4 = 0; d4 < 8; d4++) {
                ulonglong2 k2 = kp[d4];
                accA = fma2(qa[2*d4],   k2.x, accA);
                accB = fma2(qa[2*d4+1], k2.y, accB);
                accC = fma2(qb[2*d4],   k2.x, accC);
                accD = fma2(qb[2*d4+1], k2.y, accD);
            }
            float2 fa = unpack2(accA), fb = unpack2(accB);
            float2 fc = unpack2(accC), fd = unpack2(accD);
            float sA = ((fa.x + fa.y) + (fb.x + fb.y)) * scale + dc[kk * 64 + q];
            float sB = ((fc.x + fc.y) + (fd.x + fd.y)) * scale + dc[kk * 64 + 32 + q];
            sva[kk] = sA; svb[kk] = sB;
            smaxa = fmaxf(smaxa, sA);
            smaxb = fmaxf(smaxb, sB);
        }
        float mna = fmaxf(ma, smaxa);
        if (__any_sync(0xFFFFFFFFu, mna > ma)) {
            float corr = __expf(ma - mna);
            la *= corr;
            unsigned long long cc = pack2(corr, corr);
            #pragma unroll
            for (int d = 0; d < 16; d++) oa[d] = mul2(oa[d], cc);
            ma = mna;
        }
        float mnb = fmaxf(mb, smaxb);
        if (__any_sync(0xFFFFFFFFu, mnb > mb)) {
            float corr = __expf(mb - mnb);
            lb *= corr;
            unsigned long long cc = pack2(corr, corr);
            #pragma unroll
            for (int d = 0; d < 16; d++) ob[d] = mul2(ob[d], cc);
            mb = mnb;
        }
        #pragma unroll
        for (int kk = 0; kk < 8; kk++) {
            float pA = __expf(sva[kk] - ma);
            float pB = __expf(svb[kk] - mb);
            la += pA; lb += pB;
            unsigned long long p2a = pack2(pA, pA);
            unsigned long long p2b = pack2(pB, pB);
            const ulonglong2* vp = (const ulonglong2*)(Vc + kk * 256 + (h << 5));
            #pragma unroll
            for (int d4 = 0; d4 < 8; d4++) {
                ulonglong2 v2 = vp[d4];
                oa[2*d4]   = fma2(v2.x, p2a, oa[2*d4]);
                oa[2*d4+1] = fma2(v2.y, p2a, oa[2*d4+1]);
                ob[2*d4]   = fma2(v2.x, p2b, ob[2*d4]);
                ob[2*d4+1] = fma2(v2.y, p2b, ob[2*d4+1]);
            }
        }

        if (kt < 127) {
            const int nxt = cur ^ 1;
            ds[nxt][dcol * 64 + drow]       = pd.x;
            ds[nxt][(dcol + 1) * 64 + drow] = pd.y;
            cp_wait0();
        }
        __syncthreads();
    }

    float inva = 1.f / la, invb = 1.f / lb;
    float* op0 = g_AO + ((long)(b * NN + qbase + q)) * HIDD + (h << 5);
    float* op1 = g_AO + ((long)(b * NN + qbase + q + 32)) * HIDD + (h << 5);
    #pragma unroll
    for (int d4 = 0; d4 < 8; d4++) {
        float2 a0 = unpack2(oa[2*d4]), a1 = unpack2(oa[2*d4+1]);
        float2 b0 = unpack2(ob[2*d4]), b1 = unpack2(ob[2*d4+1]);
        ((float4*)op0)[d4] = make_float4(a0.x * inva, a0.y * inva, a1.x * inva, a1.y * inva);
        ((float4*)op1)[d4] = make_float4(b0.x * invb, b0.y * invb, b1.x * invb, b1.y * invb);
    }
}

// ============================================================
// Node scores: s = tanh((x . w) / ||w||). One warp per node.
// ============================================================
__global__ __launch_bounds__(256) void score_kernel(const float* __restrict__ w)
{
    int warp = (blockIdx.x * blockDim.x + threadIdx.x) >> 5;
    int lane = threadIdx.x & 31;
    if (warp >= BB * NN) return;
    const float* x = g_ENC + (long)warp * HIDD;
    float sx = 0.f, sw = 0.f;
    #pragma unroll
    for (int i = lane; i < HIDD; i += 32) {
        float wv = w[i];
        sx += x[i] * wv;
        sw += wv * wv;
    }
    #pragma unroll
    for (int off = 16; off; off >>= 1) {
        sx += __shfl_xor_sync(0xFFFFFFFFu, sx, off);
        sw += __shfl_xor_sync(0xFFFFFFFFu, sw, off);
    }
    if (lane == 0) g_score[warp] = tanhf(sx / sqrtf(sw));
}

// ============================================================
// Top-K per graph: bitonic sort of 1024 (desc score, asc index).
// ============================================================
__global__ __launch_bounds__(1024) void topk_kernel(float* __restrict__ out_perm)
{
    __shared__ unsigned long long s[NN];
    const int b = blockIdx.x, t = threadIdx.x;
    float sc = g_score[b * NN + t];
    unsigned u = __float_as_uint(sc);
    u = (u & 0x80000000u) ? ~u : (u | 0x80000000u);
    u = ~u;                                            // descending
    s[t] = (((unsigned long long)u) << 32) | (unsigned)t;
    g_nodemap[b * NN + t] = -1;
    __syncthreads();
    for (unsigned k = 2; k <= NN; k <<= 1)
        for (unsigned j = k >> 1; j; j >>= 1) {
            unsigned i = t, ixj = i ^ j;
            if (ixj > i) {
                bool up = ((i & k) == 0);
                unsigned long long a = s[i], c = s[ixj];
                if ((a > c) == up) { s[i] = c; s[ixj] = a; }
            }
            __syncthreads();
        }
    if (t < KKP) {
        int node = (int)(s[t] & 0xFFFFFFFFu);
        g_perm[b * KKP + t] = node;
        g_vals[b * KKP + t] = g_score[b * NN + node];
        out_perm[b * KKP + t] = (float)node;
        g_nodemap[b * NN + node] = t;
    }
}

// ============================================================
// sub_x gather
// ============================================================
__global__ __launch_bounds__(256) void subx_kernel(float* __restrict__ out)
{
    const int row = blockIdx.x;
    const int b = row / KKP;
    const int node = g_perm[row];
    const float val = g_vals[row];
    const float* src = g_ENC + ((long)b * NN + node) * HIDD;
    out[(long)row * HIDD + threadIdx.x] = src[threadIdx.x] * val;
}

// ============================================================
// Edge pipeline (6 kernels): build+segment-sort fused, 3 global
// merge steps, smerge, final smerge fused with emit.
// Packed: key(19b) << 21 | (ou+1)<<11 | (ov+1)<<1 | valid.
// ============================================================
__global__ __launch_bounds__(1024) void edge_sortbuild(const void* __restrict__ eiraw)
{
    __shared__ unsigned long long sh[4096];
    __shared__ int s_is64;
    const int b = blockIdx.x >> 2, seg = blockIdx.x & 3;
    const int t = threadIdx.x;
    if (t == 0) {
        const unsigned* w32 = (const unsigned*)eiraw;
        int all0 = 1;
        for (int i = 0; i < 64; i++)
            if (w32[2 * i + 1] != 0u) { all0 = 0; break; }
        s_is64 = all0;
    }
    __syncthreads();
    const int is64 = s_is64;
    const int total = BB * EPER;

    #pragma unroll
    for (int li = 0; li < 4; li++) {
        int i = t + li * 1024;              // 0..4095 local
        int idx = b * EPER + seg * 4096 + i;
        long long vs, vd;
        if (is64) {
            const long long* ei = (const long long*)eiraw;
            vs = ei[idx];
            vd = ei[total + idx];
        } else {
            const int* ei = (const int*)eiraw;
            vs = ei[idx];
            vd = ei[total + idx];
        }
        int src = (int)(vs - (long long)b * NN);
        int dst = (int)(vd - (long long)b * NN);
        src = min(max(src, 0), NN - 1);
        dst = min(max(dst, 0), NN - 1);
        int nu = g_nodemap[b * NN + src];
        int nv = g_nodemap[b * NN + dst];
        bool valid = (nu >= 0) && (nv >= 0);
        unsigned key = valid ? (unsigned)(nu * KKP + nv) : (unsigned)(KKP * KKP);
        int ou = valid ? nu : -1, ov = valid ? nv : -1;
        sh[i] = (((unsigned long long)key) << 21)
              | (((unsigned long long)(ou + 1)) << 11)
              | (((unsigned long long)(ov + 1)) << 1)
              | (valid ? 1ull : 0ull);
    }
    __syncthreads();

    for (unsigned k = 2; k <= 4096; k <<= 1)
        for (unsigned j = k >> 1; j; j >>= 1) {
            for (int loc = t; loc < 4096; loc += 1024) {
                unsigned i2 = (unsigned)loc, ixj = i2 ^ j;
                if (ixj > i2) {
                    unsigned gi = seg * 4096 + i2;
                    bool up = ((gi & k) == 0);
                    unsigned long long a = sh[i2], c = sh[ixj];
                    if ((a > c) == up) { sh[i2] = c; sh[ixj] = a; }
                }
            }
            __syncthreads();
        }
    unsigned long long* es = g_es + (long)b * EPER + seg * 4096;
    for (int i = t; i < 4096; i += 1024) es[i] = sh[i];
}

__global__ __launch_bounds__(1024) void edge_gmerge(unsigned k, unsigned j)
{
    int loc = blockIdx.x * blockDim.x + threadIdx.x;
    unsigned i = (unsigned)(loc & (EPER - 1));
    int b = loc >> 14;
    unsigned ixj = i ^ j;
    if (ixj > i) {
        unsigned long long* es = g_es + (long)b * EPER;
        bool up = ((i & k) == 0);
        unsigned long long a = es[i], c = es[ixj];
        if ((a > c) == up) { es[i] = c; es[ixj] = a; }
    }
}

__global__ __launch_bounds__(1024) void edge_smerge(unsigned k)
{
    __shared__ unsigned long long sh[4096];
    const int b = blockIdx.x >> 2, seg = blockIdx.x & 3;
    const int t = threadIdx.x;
    unsigned long long* es = g_es + (long)b * EPER + seg * 4096;
    for (int i = t; i < 4096; i += 1024) sh[i] = es[i];
    __syncthreads();
    for (unsigned j = 2048; j; j >>= 1) {
        for (int loc = t; loc < 4096; loc += 1024) {
            unsigned i2 = (unsigned)loc, ixj = i2 ^ j;
            if (ixj > i2) {
                unsigned gi = seg * 4096 + i2;
                bool up = ((gi & k) == 0);
                unsigned long long a = sh[i2], c = sh[ixj];
                if ((a > c) == up) { sh[i2] = c; sh[ixj] = a; }
            }
        }
        __syncthreads();
    }
    for (int i = t; i < 4096; i += 1024) es[i] = sh[i];
}

// Final merge tail (k = 16384, j = 2048..1) fused with emit.
__global__ __launch_bounds__(1024) void edge_smerge_emit(
    float* __restrict__ out_e, float* __restrict__ out_valid)
{
    __shared__ unsigned long long sh[4096];
    const int b = blockIdx.x >> 2, seg = blockIdx.x & 3;
    const int t = threadIdx.x;
    const unsigned k = 16384u;
    unsigned long long* es = g_es + (long)b * EPER + seg * 4096;
    for (int i = t; i < 4096; i += 1024) sh[i] = es[i];
    __syncthreads();
    for (unsigned j = 2048; j; j >>= 1) {
        for (int loc = t; loc < 4096; loc += 1024) {
            unsigned i2 = (unsigned)loc, ixj = i2 ^ j;
            if (ixj > i2) {
                unsigned gi = seg * 4096 + i2;
                bool up = ((gi & k) == 0);
                unsigned long long a = sh[i2], c = sh[ixj];
                if ((a > c) == up) { sh[i2] = c; sh[ixj] = a; }
            }
        }
        __syncthreads();
    }
    for (int i = t; i < 4096; i += 1024) {
        unsigned long long p = sh[i];
        int e = seg * 4096 + i;
        int ou = (int)((p >> 11) & 0x3FFu) - 1;
        int ov = (int)((p >> 1) & 0x3FFu) - 1;
        out_e[(long)b * 2 * EPER + e]        = (float)ou;
        out_e[(long)b * 2 * EPER + EPER + e] = (float)ov;
        out_valid[(long)b * EPER + e]        = (float)(p & 1ull);
    }
}

// ============================================================
extern "C" void kernel_launch(void* const* d_in, const int* in_sizes, int n_in,
                              void* d_out, int out_size)
{
    const float* X    = (const float*)d_in[0];
    const void*  EI   = d_in[1];
    const float* DIST = (const float*)d_in[3];
    const float* Wq   = (const float*)d_in[5];
    const float* Wk   = (const float*)d_in[6];
    const float* Wv   = (const float*)d_in[7];
    const float* Wo   = (const float*)d_in[8];
    const float* tw   = (const float*)d_in[9];
    float* out = (float*)d_out;

    // fused QKV (gridDim.z = 3 selects Wq/Wk/Wv)
    gemm_k<<<dim3(4, 64, 3), 256>>>(X, Wq, Wk, Wv, 0, out + OFF_ENC);

    attn_kernel<<<dim3(16, 8), 256>>>(DIST);

    gemm_k<<<dim3(4, 64, 1), 256>>>(X, Wo, Wo, Wo, 3, out + OFF_ENC);

    score_kernel<<<(BB * NN * 32) / 256, 256>>>(tw);
    topk_kernel<<<BB, NN>>>(out + OFF_PERM);
    subx_kernel<<<BB * KKP, 256>>>(out + OFF_SUBX);

    edge_sortbuild<<<32, 1024>>>(EI);
    edge_gmerge<<<128, 1024>>>(8192u, 4096u);
    edge_smerge<<<32, 1024>>>(8192u);
    edge_gmerge<<<128, 1024>>>(16384u, 8192u);
    edge_gmerge<<<128, 1024>>>(16384u, 4096u);
    edge_smerge_emit<<<32, 1024>>>(out + OFF_EDGE, out + OFF_VALID);
}